// round 14
// baseline (speedup 1.0000x reference)
#include <cuda_runtime.h>

#define HH 4096
#define WW 1024
#define SS 16
#define NSEG 17
#define NCHB 8            // row-blocks per column (512 rows each)
#define WIN 12.0f
#define FINF 3.0e38f

// ---- scratch (__device__ globals; zero-initialized, no allocation) ---------
__device__ float g_bsum[NCHB * WW];            // per-(row-block, column) sums
__device__ unsigned g_flag[256];               // [bw*8+bh] publish flags
__device__ float g_mag[WW];                    // per-column total mass
__device__ float g_winx[SS * WW * 32];         // 2MB: window rows, [b][w][slot]
// hard partials, dense layout [bh][s][w]
__device__ float g_hB[NCHB * NSEG * WW];
__device__ float g_hA[NCHB * NSEG * WW];
__device__ float g_hC[NCHB * NSEG * WW];
__device__ float g_sum, g_cnt;
__device__ unsigned g_ticket;

// data-independent per-segment reference (bit-identical in both kernels)
__device__ __forceinline__ float seg_ref(float sL, float sR) {
    return (sL + sR) * (0.5f / (float)HH);
}

// ---------------------------------------------------------------------------
// K1: fused partial-sums + main sweep. Block (bw,bh) = 32 cols x 512 rows,
// warp v = 64-row chunk, lane = column. Pass 1: block-column sums + flag
// sync within the column group. Pass 2: normalized cumsum; hard moments
// about snake-derived refs; window rows stored COMPACTLY into g_winx
// (scattered stores are cheap; the reads in K2 become coalesced).
// ---------------------------------------------------------------------------
__global__ void __launch_bounds__(256, 2) k_sweep(const float* __restrict__ preds,
                                                  const float* __restrict__ snakes) {
    __shared__ float s_chunk[8][32];
    __shared__ float snk[SS][32];
    __shared__ float accB[NSEG][32], accA[NSEG][32], accC[NSEG][32];

    const int bw = blockIdx.x, bh = blockIdx.y;
    const int tid = threadIdx.x;
    const int v = tid >> 5, lane = tid & 31;
    const int col = bw * 32 + lane;

    if (bw == 0 && bh == 0 && tid == 0) { g_sum = 0.f; g_cnt = 0.f; g_ticket = 0u; }

    for (int e = tid; e < SS * 32; e += 256)
        snk[e >> 5][e & 31] = snakes[(e >> 5) * WW + bw * 32 + (e & 31)];
    for (int e = tid; e < NSEG * 32; e += 256) {
        accB[e >> 5][e & 31] = 0.f;
        accA[e >> 5][e & 31] = 0.f;
        accC[e >> 5][e & 31] = 0.f;
    }

    const int h0 = (bh * 8 + v) * 64;
    const float* p = preds + (size_t)h0 * WW + col;

    // ---- pass 1: chunk sum (16 independent loads per batch) ----
    float csum = 0.f;
#pragma unroll
    for (int b = 0; b < 4; b++) {
        float r0 = 0.f, r1 = 0.f, r2 = 0.f, r3 = 0.f;
#pragma unroll
        for (int k = 0; k < 16; k += 4) {
            r0 += p[(size_t)(b * 16 + k + 0) * WW];
            r1 += p[(size_t)(b * 16 + k + 1) * WW];
            r2 += p[(size_t)(b * 16 + k + 2) * WW];
            r3 += p[(size_t)(b * 16 + k + 3) * WW];
        }
        csum += (r0 + r1) + (r2 + r3);
    }
    s_chunk[v][lane] = csum;
    __syncthreads();

    if (tid < 32) {
        float bsum = 0.f;
#pragma unroll
        for (int v2 = 0; v2 < 8; v2++) bsum += s_chunk[v2][tid];
        g_bsum[bh * WW + bw * 32 + tid] = bsum;
    }
    __syncthreads();
    if (tid == 0) {
        __threadfence();
        atomicExch(&g_flag[bw * NCHB + bh], 1u);
    }
    if (tid < NCHB) {
        volatile unsigned* f = &g_flag[bw * NCHB + tid];
        while (*f == 0u) __nanosleep(20);
        __threadfence();
    }
    __syncthreads();

    // ---- base / mag ----
    float base = 0.f, mag = 0.f;
#pragma unroll
    for (int i = 0; i < NCHB; i++) {
        float bs = g_bsum[i * WW + col];
        base += (i < bh) ? bs : 0.f;
        mag += bs;
    }
#pragma unroll
    for (int v2 = 0; v2 < 8; v2++)
        base += (v2 < v) ? s_chunk[v2][lane] : 0.f;
    const float inv = 1.0f / mag;
    if (bh == 0 && tid < 32) g_mag[col] = mag;

    // ---- pass 2: scan + compact window stores + hard moments ----
    int j = 0;
    while (j < SS && snk[j][lane] <= (float)h0) j++;
    float sL = (j > 0) ? snk[j - 1][lane] : 0.f;
    float sR = (j < SS) ? snk[j][lane] : (float)HH;
    float ref = seg_ref(sL, sR);
    float sNext = (j < SS) ? sR : FINF;

    float cum = base;
    float A = 0.f, C = 0.f, B = 0.f;

#pragma unroll
    for (int b = 0; b < 4; b++) {
        float regs[16];
#pragma unroll
        for (int k = 0; k < 16; k++)
            regs[k] = p[(size_t)(b * 16 + k) * WW];
#pragma unroll
        for (int k = 0; k < 16; k++) {
            const int r = b * 16 + k;
            cum += regs[k];
            const float x = cum * inv;
            const float hf = (float)(h0 + r);
            if (hf >= sNext) {                       // segment crossed
                if (B > 0.f) {
                    atomicAdd(&accB[j][lane], B);
                    atomicAdd(&accA[j][lane], A);
                    atomicAdd(&accC[j][lane], C);
                }
                A = C = B = 0.f;
                j++;
                while (j < SS && snk[j][lane] <= hf) j++;
                sL = snk[j - 1][lane];
                sR = (j < SS) ? snk[j][lane] : (float)HH;
                ref = seg_ref(sL, sR);
                sNext = (j < SS) ? sR : FINF;
            }
            // window stores: walk boundaries below (b2=j-1,j-2,..) and above
            // (b2=j,j+1,..) while within WIN — covers clustered boundaries.
            if (j > 0 && hf - sL <= WIN) {
                int b2 = j - 1;
                do {
                    float sb = snk[b2][lane];
                    if (sb < hf - WIN) break;
                    int lo = max(0, (int)ceilf(sb - WIN));
                    g_winx[((size_t)b2 * WW + col) * 32 + (h0 + r - lo)] = x;
                    b2--;
                } while (b2 >= 0);
            }
            if (sNext - hf <= WIN) {                 // implies j < SS
                int b2 = j;
                do {
                    float sb = snk[b2][lane];
                    if (sb > hf + WIN) break;
                    int lo = max(0, (int)ceilf(sb - WIN));
                    g_winx[((size_t)b2 * WW + col) * 32 + (h0 + r - lo)] = x;
                    b2++;
                } while (b2 < SS);
            }
            float dx = x - ref;
            A += dx; C = fmaf(dx, dx, C); B += 1.f;
        }
    }
    if (B > 0.f) {
        atomicAdd(&accB[j][lane], B);
        atomicAdd(&accA[j][lane], A);
        atomicAdd(&accC[j][lane], C);
    }
    __syncthreads();

    // dense coalesced partial write: [bh][s][w]
    for (int e = tid; e < NSEG * 32; e += 256) {
        int s = e >> 5, l = e & 31;
        size_t o = ((size_t)bh * NSEG + s) * WW + bw * 32 + l;
        g_hB[o] = accB[s][l];
        g_hA[o] = accA[s][l];
        g_hC[o] = accC[s][l];
    }
}

// ---------------------------------------------------------------------------
// K2: block per column w. Phase 1: warp wid computes boundaries wid, wid+8 —
// window rows now COALESCED from g_winx (one 128B line each). Phase 2:
// threads 0..16 combine segments. Warp 0 reduces, ticket-finalizes.
// Also resets K1's flags for the next graph replay.
// ---------------------------------------------------------------------------
__global__ void __launch_bounds__(256) k_fin(const float* __restrict__ snakes,
                                             float* __restrict__ out) {
    __shared__ float s_snk[SS];
    __shared__ float sw0[SS], sw1[SS], sw2[SS];
    __shared__ float sV[32];

    const int w = blockIdx.x;
    const int tid = threadIdx.x;
    const int wid = tid >> 5, lane = tid & 31;

    if (w == 0) g_flag[tid] = 0u;     // reset for next replay
    if (tid < SS) s_snk[tid] = snakes[tid * WW + w];
    if (tid < 32) sV[tid] = 0.f;
    __syncthreads();

    // ---- phase 1: 2 windows per warp, coalesced loads ----
#pragma unroll
    for (int bb = 0; bb < 2; bb++) {
        const int b = wid + bb * 8;
        const float sp = s_snk[b];
        const int lo = max(0, (int)ceilf(sp - WIN));
        const int hi = min(HH, (int)floorf(sp + WIN) + 1);
        float d0 = 0.f, d1 = 0.f, d2 = 0.f;
        if (lane < hi - lo) {
            const int h = lo + lane;
            float t = sp - (float)h;
            float e = __expf(-fabsf(t));
            float sg = e / (1.f + e);
            float dlt = (t > 0.f) ? -sg : sg;   // sigmoid - step, stable
            float x = g_winx[((size_t)b * WW + w) * 32 + lane];
            d0 = dlt; d1 = dlt * x; d2 = dlt * x * x;
        }
#pragma unroll
        for (int d = 16; d; d >>= 1) {
            d0 += __shfl_xor_sync(0xffffffffu, d0, d);
            d1 += __shfl_xor_sync(0xffffffffu, d1, d);
            d2 += __shfl_xor_sync(0xffffffffu, d2, d);
        }
        if (lane == 0) { sw0[b] = d0; sw1[b] = d1; sw2[b] = d2; }
    }
    __syncthreads();

    // ---- phase 2: per-segment combine (threads 0..16) ----
    if (tid < NSEG) {
        const int s = tid;
        float B = 0.f, A = 0.f, C = 0.f;
#pragma unroll
        for (int bh = 0; bh < NCHB; bh++) {
            size_t idx = ((size_t)bh * NSEG + s) * WW + w;
            B += g_hB[idx]; A += g_hA[idx]; C += g_hC[idx];
        }
        float sL = (s > 0)  ? s_snk[s - 1] : 0.f;
        float sR = (s < SS) ? s_snk[s]     : (float)HH;
        float ref = seg_ref(sL, sR);

        float mean = ref, M2 = 0.f;
        if (B > 0.f) { mean = ref + A / B; M2 = C - A * A / B; }

        float D0 = 0.f, D1 = 0.f, D2 = 0.f;
        if (s < SS) { D0 += sw0[s]; D1 += sw1[s]; D2 += sw2[s]; }
        if (s > 0)  { D0 -= sw0[s - 1]; D1 -= sw1[s - 1]; D2 -= sw2[s - 1]; }

        float d1c = D1 - mean * D0;
        float d2c = D2 - 2.f * mean * D1 + mean * mean * D0;
        float Bt = B + D0;
        sV[tid] = (Bt > 1e-12f) ? (M2 + d2c) - d1c * d1c / Bt : 0.f;
    }
    __syncthreads();

    // ---- reduce, mask, accumulate, finalize ----
    if (tid < 32) {
        float vv = sV[tid];
#pragma unroll
        for (int d = 16; d; d >>= 1)
            vv += __shfl_xor_sync(0xffffffffu, vv, d);
        if (tid == 0) {
            bool mask = g_mag[w] > 1.0f;
            atomicAdd(&g_sum, mask ? vv : 0.f);
            atomicAdd(&g_cnt, mask ? 1.f : 0.f);
            __threadfence();
            unsigned t = atomicAdd(&g_ticket, 1u);
            if (t == gridDim.x - 1)
                out[0] = g_sum / ((float)(NSEG * HH)) / g_cnt;
        }
    }
}

// ---------------------------------------------------------------------------
extern "C" void kernel_launch(void* const* d_in, const int* in_sizes, int n_in,
                              void* d_out, int out_size) {
    const float* snakes = (const float*)d_in[0];   // [16, 1024]
    const float* preds  = (const float*)d_in[1];   // [4096, 1024]
    (void)in_sizes; (void)n_in; (void)out_size;

    k_sweep<<<dim3(WW / 32, NCHB), 256>>>(preds, snakes);
    k_fin<<<WW, 256>>>(snakes, (float*)d_out);
}

// round 15
// speedup vs baseline: 1.7135x; 1.7135x over previous
#include <cuda_runtime.h>

#define HH 4096
#define WW 1024
#define SS 16
#define NSEG 17
#define NCHB 8            // row-blocks per column (512 rows each)
#define WIN 12.0f
#define FINF 3.0e38f

// ---- scratch (__device__ globals; zero-initialized, no allocation) ---------
__device__ float g_bsum[NCHB * WW];            // per-(row-block, column) sums
__device__ unsigned g_flag[256];               // [bw*8+bh] publish flags
__device__ float g_mag[WW];                    // per-column total mass
__device__ float g_cum[HH * WW];               // normalized cumsum (window rows only)
__device__ float4 g_hP[NCHB * NSEG * WW];      // hard partials (B,A,C,-), [bh][s][w]
__device__ float g_sum, g_cnt;
__device__ unsigned g_ticket;

// data-independent per-segment reference (bit-identical in both kernels)
__device__ __forceinline__ float seg_ref(float sL, float sR) {
    return (sL + sR) * (0.5f / (float)HH);
}

// ---------------------------------------------------------------------------
// K1: fused partial-sums + main sweep. Block (bw,bh) = 32 cols x 512 rows,
// warp v = 64-row chunk, lane = column. Pass 1: block-column sums + flag
// sync within column group. Pass 2: normalized cumsum; predicated g_cum
// stores (window rows only); hard moments about snake-derived refs.
// ---------------------------------------------------------------------------
__global__ void __launch_bounds__(256, 2) k_sweep(const float* __restrict__ preds,
                                                  const float* __restrict__ snakes) {
    __shared__ float s_chunk[8][32];
    __shared__ float snk[SS][32];
    __shared__ float accB[NSEG][32], accA[NSEG][32], accC[NSEG][32];

    const int bw = blockIdx.x, bh = blockIdx.y;
    const int tid = threadIdx.x;
    const int v = tid >> 5, lane = tid & 31;
    const int col = bw * 32 + lane;

    if (bw == 0 && bh == 0 && tid == 0) { g_sum = 0.f; g_cnt = 0.f; g_ticket = 0u; }

    for (int e = tid; e < SS * 32; e += 256)
        snk[e >> 5][e & 31] = snakes[(e >> 5) * WW + bw * 32 + (e & 31)];
    for (int e = tid; e < NSEG * 32; e += 256) {
        accB[e >> 5][e & 31] = 0.f;
        accA[e >> 5][e & 31] = 0.f;
        accC[e >> 5][e & 31] = 0.f;
    }

    const int h0 = (bh * 8 + v) * 64;
    const float* p = preds + (size_t)h0 * WW + col;

    // ---- pass 1: chunk sum (16 independent loads per batch) ----
    float csum = 0.f;
#pragma unroll
    for (int b = 0; b < 4; b++) {
        float r0 = 0.f, r1 = 0.f, r2 = 0.f, r3 = 0.f;
#pragma unroll
        for (int k = 0; k < 16; k += 4) {
            r0 += p[(size_t)(b * 16 + k + 0) * WW];
            r1 += p[(size_t)(b * 16 + k + 1) * WW];
            r2 += p[(size_t)(b * 16 + k + 2) * WW];
            r3 += p[(size_t)(b * 16 + k + 3) * WW];
        }
        csum += (r0 + r1) + (r2 + r3);
    }
    s_chunk[v][lane] = csum;
    __syncthreads();

    if (tid < 32) {
        float bsum = 0.f;
#pragma unroll
        for (int v2 = 0; v2 < 8; v2++) bsum += s_chunk[v2][tid];
        g_bsum[bh * WW + bw * 32 + tid] = bsum;
    }
    __syncthreads();
    if (tid == 0) {
        __threadfence();
        atomicExch(&g_flag[bw * NCHB + bh], 1u);
    }
    if (tid < NCHB) {
        volatile unsigned* f = &g_flag[bw * NCHB + tid];
        while (*f == 0u) __nanosleep(20);
        __threadfence();
    }
    __syncthreads();

    // ---- base / mag ----
    float base = 0.f, mag = 0.f;
#pragma unroll
    for (int i = 0; i < NCHB; i++) {
        float bs = g_bsum[i * WW + col];
        base += (i < bh) ? bs : 0.f;
        mag += bs;
    }
#pragma unroll
    for (int v2 = 0; v2 < 8; v2++)
        base += (v2 < v) ? s_chunk[v2][lane] : 0.f;
    const float inv = 1.0f / mag;
    if (bh == 0 && tid < 32) g_mag[col] = mag;

    // ---- pass 2: scan + predicated g_cum stores + hard moments ----
    float* outc = g_cum + (size_t)h0 * WW + col;

    int j = 0;
    while (j < SS && snk[j][lane] <= (float)h0) j++;
    float sL = (j > 0) ? snk[j - 1][lane] : 0.f;
    float sR = (j < SS) ? snk[j][lane] : (float)HH;
    float ref = seg_ref(sL, sR);
    float sNext = (j < SS) ? sR : FINF;

    float cum = base;
    float A = 0.f, C = 0.f, B = 0.f;

#pragma unroll
    for (int b = 0; b < 4; b++) {
        float regs[16];
#pragma unroll
        for (int k = 0; k < 16; k++)
            regs[k] = p[(size_t)(b * 16 + k) * WW];
#pragma unroll
        for (int k = 0; k < 16; k++) {
            const int r = b * 16 + k;
            cum += regs[k];
            const float x = cum * inv;
            const float hf = (float)(h0 + r);
            if (hf >= sNext) {                       // segment crossed
                if (B > 0.f) {
                    atomicAdd(&accB[j][lane], B);
                    atomicAdd(&accA[j][lane], A);
                    atomicAdd(&accC[j][lane], C);
                }
                A = C = B = 0.f;
                j++;
                while (j < SS && snk[j][lane] <= hf) j++;
                sL = snk[j - 1][lane];
                sR = (j < SS) ? snk[j][lane] : (float)HH;
                ref = seg_ref(sL, sR);
                sNext = (j < SS) ? sR : FINF;
            }
            // store only rows the window pass will read (predicated, no branch)
            if ((hf - sL <= WIN) || (sNext - hf <= WIN))
                outc[(size_t)r * WW] = x;
            float dx = x - ref;
            A += dx; C = fmaf(dx, dx, C); B += 1.f;
        }
    }
    if (B > 0.f) {
        atomicAdd(&accB[j][lane], B);
        atomicAdd(&accA[j][lane], A);
        atomicAdd(&accC[j][lane], C);
    }
    __syncthreads();

    // packed coalesced partial write: [bh][s][w], 128-bit stores
    for (int e = tid; e < NSEG * 32; e += 256) {
        int s = e >> 5, l = e & 31;
        size_t o = ((size_t)bh * NSEG + s) * WW + bw * 32 + l;
        g_hP[o] = make_float4(accB[s][l], accA[s][l], accC[s][l], 0.f);
    }
}

// ---------------------------------------------------------------------------
// K2: block per column w. Phase 1: warp wid computes windows wid and wid+8
// once each (lane = row; results in smem). Phase 2: threads 0..16 combine
// segments (8 float4 loads each). Warp 0 reduces, ticket-finalizes.
// Also resets K1's flags for the next graph replay.
// ---------------------------------------------------------------------------
__global__ void __launch_bounds__(256) k_fin(const float* __restrict__ snakes,
                                             float* __restrict__ out) {
    __shared__ float s_snk[SS];
    __shared__ float sw0[SS], sw1[SS], sw2[SS];
    __shared__ float sV[32];

    const int w = blockIdx.x;
    const int tid = threadIdx.x;
    const int wid = tid >> 5, lane = tid & 31;

    if (w == 0) g_flag[tid] = 0u;     // reset for next replay
    if (tid < SS) s_snk[tid] = snakes[tid * WW + w];
    if (tid < 32) sV[tid] = 0.f;
    __syncthreads();

    // ---- phase 1: each warp computes 2 boundary windows (each ONCE) ----
#pragma unroll
    for (int bb = 0; bb < 2; bb++) {
        const int b = wid + bb * 8;
        const float sp = s_snk[b];
        const int lo = max(0, (int)ceilf(sp - WIN));
        const int hi = min(HH, (int)floorf(sp + WIN) + 1);
        float d0 = 0.f, d1 = 0.f, d2 = 0.f;
        const int h = lo + lane;
        if (h < hi) {
            float t = sp - (float)h;
            float e = __expf(-fabsf(t));
            float sg = e / (1.f + e);
            float dlt = (t > 0.f) ? -sg : sg;   // sigmoid - step, stable
            float x = g_cum[(size_t)h * WW + w];
            d0 = dlt; d1 = dlt * x; d2 = dlt * x * x;
        }
#pragma unroll
        for (int d = 16; d; d >>= 1) {
            d0 += __shfl_xor_sync(0xffffffffu, d0, d);
            d1 += __shfl_xor_sync(0xffffffffu, d1, d);
            d2 += __shfl_xor_sync(0xffffffffu, d2, d);
        }
        if (lane == 0) { sw0[b] = d0; sw1[b] = d1; sw2[b] = d2; }
    }
    __syncthreads();

    // ---- phase 2: per-segment combine (threads 0..16, 8 float4 loads) ----
    if (tid < NSEG) {
        const int s = tid;
        float B = 0.f, A = 0.f, C = 0.f;
#pragma unroll
        for (int bh = 0; bh < NCHB; bh++) {
            float4 pq = g_hP[((size_t)bh * NSEG + s) * WW + w];
            B += pq.x; A += pq.y; C += pq.z;
        }
        float sL = (s > 0)  ? s_snk[s - 1] : 0.f;
        float sR = (s < SS) ? s_snk[s]     : (float)HH;
        float ref = seg_ref(sL, sR);

        float mean = ref, M2 = 0.f;
        if (B > 0.f) { mean = ref + A / B; M2 = C - A * A / B; }

        float D0 = 0.f, D1 = 0.f, D2 = 0.f;
        if (s < SS) { D0 += sw0[s]; D1 += sw1[s]; D2 += sw2[s]; }
        if (s > 0)  { D0 -= sw0[s - 1]; D1 -= sw1[s - 1]; D2 -= sw2[s - 1]; }

        float d1c = D1 - mean * D0;
        float d2c = D2 - 2.f * mean * D1 + mean * mean * D0;
        float Bt = B + D0;
        sV[tid] = (Bt > 1e-12f) ? (M2 + d2c) - d1c * d1c / Bt : 0.f;
    }
    __syncthreads();

    // ---- reduce 17 values, mask, accumulate, finalize ----
    if (tid < 32) {
        float vv = sV[tid];
#pragma unroll
        for (int d = 16; d; d >>= 1)
            vv += __shfl_xor_sync(0xffffffffu, vv, d);
        if (tid == 0) {
            bool mask = g_mag[w] > 1.0f;
            atomicAdd(&g_sum, mask ? vv : 0.f);
            atomicAdd(&g_cnt, mask ? 1.f : 0.f);
            __threadfence();
            unsigned t = atomicAdd(&g_ticket, 1u);
            if (t == gridDim.x - 1)
                out[0] = g_sum / ((float)(NSEG * HH)) / g_cnt;
        }
    }
}

// ---------------------------------------------------------------------------
extern "C" void kernel_launch(void* const* d_in, const int* in_sizes, int n_in,
                              void* d_out, int out_size) {
    const float* snakes = (const float*)d_in[0];   // [16, 1024]
    const float* preds  = (const float*)d_in[1];   // [4096, 1024]
    (void)in_sizes; (void)n_in; (void)out_size;

    k_sweep<<<dim3(WW / 32, NCHB), 256>>>(preds, snakes);
    k_fin<<<WW, 256>>>(snakes, (float*)d_out);
}